// round 1
// baseline (speedup 1.0000x reference)
#include <cuda_runtime.h>

#define NS   128   // states
#define NT   2048  // time steps
#define NB   64    // batch
#define NDM  128   // max duration

// Shared memory layout (floats):
//   sA   [128*128]  exp(A_logits), row-major [i][j]
//   sDT  [128*128]  exp(D_logits) transposed: [d][j]
//   ring [128*128]  exp-domain entry ring:    [slot][j]  (thread j owns column j)
//   p_sh [128]      exp(alpha - m)
//   wred [8]        cross-warp reduction scratch
#define SMEM_FLOATS (16384*3 + 128 + 8)

__global__ __launch_bounds__(128, 1)
void hsmm_fwd_kernel(const float* __restrict__ logB,
                     const float* __restrict__ pi,
                     const float* __restrict__ A,
                     const float* __restrict__ D,
                     float* __restrict__ out)
{
    extern __shared__ float sm[];
    float* sA   = sm;
    float* sDT  = sm + 16384;
    float* ring = sm + 32768;
    float* p_sh = sm + 49152;
    float* wred = sm + 49280;

    const int j    = threadIdx.x;      // state index
    const int b    = blockIdx.x;       // batch index
    const int lane = j & 31;
    const int wid  = j >> 5;

    // Build exp(A) row-major, exp(D)^T [d][j], zero the ring.
    for (int idx = j; idx < 16384; idx += 128) {
        sA[idx] = __expf(A[idx]);                 // A[i*128+j]
        int d = idx >> 7, jj = idx & 127;
        sDT[idx] = __expf(D[jj * NDM + d]);       // sDT[d*128+j] = exp(D[j][d])
        ring[idx] = 0.0f;
    }
    __syncthreads();

    float cum  = 0.0f, cumc = 0.0f;   // Kahan-compensated cumulative emission sum (state j)
    float ref  = 0.0f;                // exp-domain reference for ring column j
    float alpha = 0.0f;               // alpha[t-1, j]
    const float* lbp = logB + (size_t)b * NT * NS + j;
    float lb_cur = lbp[0];
    const float pij = pi[j];

    for (int t = 0; t < NT; ++t) {
        float lb_next = (t + 1 < NT) ? lbp[(size_t)(t + 1) * NS] : 0.0f;  // prefetch

        float entry;
        if (t == 0) {
            entry = pij;
        } else {
            // block max of alpha
            float v = alpha;
            #pragma unroll
            for (int o = 16; o > 0; o >>= 1)
                v = fmaxf(v, __shfl_xor_sync(0xffffffffu, v, o));
            if (lane == 0) wred[wid] = v;
            __syncthreads();
            float m = fmaxf(fmaxf(wred[0], wred[1]), fmaxf(wred[2], wred[3]));
            p_sh[j] = __expf(alpha - m);
            __syncthreads();
            // trans_j = m + log( sum_i p[i] * expA[i][j] )   (real matvec)
            float s0 = 0.f, s1 = 0.f, s2 = 0.f, s3 = 0.f;
            #pragma unroll 8
            for (int i = 0; i < NS; i += 4) {
                float4 pv = *(const float4*)(p_sh + i);
                s0 = fmaf(pv.x, sA[(i + 0) * NS + j], s0);
                s1 = fmaf(pv.y, sA[(i + 1) * NS + j], s1);
                s2 = fmaf(pv.z, sA[(i + 2) * NS + j], s2);
                s3 = fmaf(pv.w, sA[(i + 3) * NS + j], s3);
            }
            float tdot = (s0 + s1) + (s2 + s3);
            entry = m + __logf(tdot);   // __logf(0) = -inf handled downstream
        }

        // Insert E = entry - cum[t] into exp-domain ring with floating reference.
        float E = entry - cum;
        float x = E - ref;
        if (x > 30.0f) {               // rescale ring down to new reference E
            float f = __expf(ref - E); // tiny factor; old content shrinks (negligible terms)
            #pragma unroll 4
            for (int s = 0; s < NDM; ++s) ring[s * NS + j] *= f;
            ref = E; x = 0.0f;
        }
        const int slot0 = t & 127;
        ring[slot0 * NS + j] = __expf(x);   // exp(-inf) = 0 is correct for dead entries

        // dot_j = sum_{d=1..128} ring[(t+1-d)&127][j] * expD[j][d]
        float d0 = 0.f, d1 = 0.f, d2 = 0.f, d3 = 0.f;
        {
            const float* rj = ring + j;
            const float* dj = sDT + j;
            int dd = 0;
            for (; dd + 3 <= slot0; dd += 4) {   // slot = slot0 - dd (no wrap)
                d0 = fmaf(rj[(slot0 - dd    ) * NS], dj[(dd    ) * NS], d0);
                d1 = fmaf(rj[(slot0 - dd - 1) * NS], dj[(dd + 1) * NS], d1);
                d2 = fmaf(rj[(slot0 - dd - 2) * NS], dj[(dd + 2) * NS], d2);
                d3 = fmaf(rj[(slot0 - dd - 3) * NS], dj[(dd + 3) * NS], d3);
            }
            for (; dd <= slot0; ++dd)
                d0 = fmaf(rj[(slot0 - dd) * NS], dj[dd * NS], d0);
            int dd2 = slot0 + 1;                 // slot = slot0 - dd + 128 (wrapped)
            for (; dd2 + 3 < NDM; dd2 += 4) {
                d0 = fmaf(rj[(slot0 - dd2 + 128) * NS], dj[(dd2    ) * NS], d0);
                d1 = fmaf(rj[(slot0 - dd2 + 127) * NS], dj[(dd2 + 1) * NS], d1);
                d2 = fmaf(rj[(slot0 - dd2 + 126) * NS], dj[(dd2 + 2) * NS], d2);
                d3 = fmaf(rj[(slot0 - dd2 + 125) * NS], dj[(dd2 + 3) * NS], d3);
            }
            for (; dd2 < NDM; ++dd2)
                d0 = fmaf(rj[(slot0 - dd2 + 128) * NS], dj[dd2 * NS], d0);
        }
        float dot = (d0 + d1) + (d2 + d3);

        // Prophylactic up-rescale if ring content decayed far below ref.
        if (dot < 1e-30f && dot > 0.0f) {
            #pragma unroll 4
            for (int s = 0; s < NDM; ++s) ring[s * NS + j] *= 1e30f;
            ref -= 69.07755279f;   // ln(1e30)
            dot *= 1e30f;
        }

        // cum[t+1] = cum[t] + lb[t]  (Kahan)
        float y  = lb_cur - cumc;
        float tt = cum + y;
        cumc = (tt - cum) - y;
        cum  = tt;

        alpha = cum + ref + __logf(dot);
        lb_cur = lb_next;
    }

    // loglik[b] = LSE_j alpha[T-1, j]
    __syncthreads();
    float v = alpha;
    #pragma unroll
    for (int o = 16; o > 0; o >>= 1)
        v = fmaxf(v, __shfl_xor_sync(0xffffffffu, v, o));
    if (lane == 0) wred[wid] = v;
    __syncthreads();
    float m = fmaxf(fmaxf(wred[0], wred[1]), fmaxf(wred[2], wred[3]));
    float e = __expf(alpha - m);
    #pragma unroll
    for (int o = 16; o > 0; o >>= 1)
        e += __shfl_xor_sync(0xffffffffu, e, o);
    if (lane == 0) wred[4 + wid] = e;
    __syncthreads();
    if (j == 0) {
        float ssum = (wred[4] + wred[5]) + (wred[6] + wred[7]);
        out[b] = m + __logf(ssum);
    }
}

extern "C" void kernel_launch(void* const* d_in, const int* in_sizes, int n_in,
                              void* d_out, int out_size)
{
    const float* logB = (const float*)d_in[0];
    const float* pi   = (const float*)d_in[1];
    const float* A    = (const float*)d_in[2];
    const float* D    = (const float*)d_in[3];
    float* out = (float*)d_out;

    const size_t smem_bytes = (size_t)SMEM_FLOATS * sizeof(float);  // ~193 KB
    cudaFuncSetAttribute(hsmm_fwd_kernel,
                         cudaFuncAttributeMaxDynamicSharedMemorySize,
                         (int)smem_bytes);
    hsmm_fwd_kernel<<<NB, NS, smem_bytes>>>(logB, pi, A, D, out);
}

// round 2
// speedup vs baseline: 1.5289x; 1.5289x over previous
#include <cuda_runtime.h>

#define NS   128   // states
#define NT   2048  // time steps
#define NB   64    // batch
#define NDM  128   // max duration

// Shared memory (floats):
//   ring [256*128]  mirrored exp-domain entry ring: [phys_slot][j]
//   p_sh [128]      exp(alpha - m)
//   pmat [512]      trans matvec partials, [j*4 + h]
//   pdur [512]      duration dot partials, [j*4 + h]
//   wredU[16]       per-warp max keys (uint, monotone float encoding)
#define RING_F   (256 * 128)
#define OFF_PSH  (RING_F)
#define OFF_PMAT (OFF_PSH + 128)
#define OFF_PDUR (OFF_PMAT + 512)
#define OFF_WRED (OFF_PDUR + 512)
#define SMEM_FLOATS (OFF_WRED + 16)

__device__ __forceinline__ unsigned f2key(float x) {
    int i = __float_as_int(x);
    return (unsigned)(i ^ ((i >> 31) | 0x80000000));
}
__device__ __forceinline__ float key2f(unsigned k) {
    int i = ((int)k < 0) ? (int)(k ^ 0x80000000u) : (int)(~k);
    return __int_as_float(i);
}

__global__ __launch_bounds__(512, 1)
void hsmm_fwd_kernel(const float* __restrict__ logB,
                     const float* __restrict__ pi,
                     const float* __restrict__ A,
                     const float* __restrict__ D,
                     float* __restrict__ out)
{
    extern __shared__ float sm[];
    float*    ring  = sm;
    float*    p_sh  = sm + OFF_PSH;
    float*    pmat  = sm + OFF_PMAT;
    float*    pdur  = sm + OFF_PDUR;
    unsigned* wredU = (unsigned*)(sm + OFF_WRED);

    const int tid  = threadIdx.x;
    const int j    = tid & 127;        // state
    const int h    = tid >> 7;         // split-K slice 0..3
    const int lane = tid & 31;
    const int w    = tid >> 5;         // warp id 0..15
    const int b    = blockIdx.x;

    // Preload weight tables into registers (no smem copies of A/D at all).
    float eA[32];   // exp(A[i][j]) for i in [32h, 32h+32)
    float eD[32];   // exp(D[j][d-1]) for d-1 in [32h, 32h+32)
    #pragma unroll
    for (int k = 0; k < 32; ++k) {
        eA[k] = __expf(A[(32 * h + k) * NS + j]);
        eD[k] = __expf(D[j * NDM + 32 * h + k]);
    }

    // Zero mirrored ring.
    for (int idx = tid; idx < RING_F; idx += 512) ring[idx] = 0.0f;
    __syncthreads();

    // Per-state scalars, replicated bit-identically across the 4 h-threads.
    float cum = 0.0f, cumc = 0.0f;     // Kahan cumulative emission sum
    float ref = 0.0f;                  // exp-domain reference for ring column j
    float alpha = 0.0f;
    const float* lbp = logB + (size_t)b * NT * NS + j;
    float lb_cur = lbp[0];
    const float pij = pi[j];

    for (int t = 0; t < NT; ++t) {
        float lb_next = (t + 1 < NT) ? lbp[(size_t)(t + 1) * NS] : 0.0f;

        float entry;
        if (t == 0) {
            entry = pij;
        } else {
            // Block max of alpha via redux.sync on monotone uint key.
            unsigned u = f2key(alpha);
            unsigned r;
            asm volatile("redux.sync.max.u32 %0, %1, 0xffffffff;" : "=r"(r) : "r"(u));
            if (lane == 0) wredU[w] = r;
            __syncthreads();                                   // BAR A
            unsigned m0 = max(max(wredU[0], wredU[1]), max(wredU[2], wredU[3]));
            float m = key2f(m0);
            if (h == 0) p_sh[j] = __expf(alpha - m);
            __syncthreads();                                   // BAR B
            // trans partial: sum over i in [32h, 32h+32)
            float s0 = 0.f, s1 = 0.f, s2 = 0.f, s3 = 0.f;
            const float4* pp = (const float4*)(p_sh + 32 * h);
            #pragma unroll
            for (int q = 0; q < 8; ++q) {
                float4 pv = pp[q];
                s0 = fmaf(pv.x, eA[4 * q + 0], s0);
                s1 = fmaf(pv.y, eA[4 * q + 1], s1);
                s2 = fmaf(pv.z, eA[4 * q + 2], s2);
                s3 = fmaf(pv.w, eA[4 * q + 3], s3);
            }
            pmat[j * 4 + h] = (s0 + s1) + (s2 + s3);
            __syncthreads();                                   // BAR C
            float4 pm = *(const float4*)(pmat + j * 4);
            entry = m + __logf((pm.x + pm.y) + (pm.z + pm.w));
        }

        const int slot0 = t & 127;

        // Insert E = entry - cum into exp-domain ring (floating reference).
        float E = entry - cum;
        float x = E - ref;
        if (x > 30.0f) {            // down-rescale old content to new ref = E
            float f = __expf(ref - E);
            #pragma unroll 1
            for (int s = 64 * h; s < 64 * h + 64; ++s)
                if ((s & 127) != slot0) ring[s * NS + j] *= f;
            ref = E; x = 0.0f;
        }
        if (h == 0) {
            float ex = __expf(x);
            ring[slot0 * NS + j] = ex;            // primary
            ring[(slot0 + 128) * NS + j] = ex;    // mirror
        }
        __syncthreads();                                       // BAR D

        // Duration dot partial: dd = 32h + k, phys slot = slot0+128-dd (no wrap).
        {
            const float* rp = ring + (slot0 + 128 - 32 * h) * NS + j;
            float d0 = 0.f, d1 = 0.f, d2 = 0.f, d3 = 0.f;
            #pragma unroll
            for (int k = 0; k < 32; k += 4) {
                d0 = fmaf(rp[-(k + 0) * NS], eD[k + 0], d0);
                d1 = fmaf(rp[-(k + 1) * NS], eD[k + 1], d1);
                d2 = fmaf(rp[-(k + 2) * NS], eD[k + 2], d2);
                d3 = fmaf(rp[-(k + 3) * NS], eD[k + 3], d3);
            }
            pdur[j * 4 + h] = (d0 + d1) + (d2 + d3);
        }
        __syncthreads();                                       // BAR E
        float4 pd = *(const float4*)(pdur + j * 4);
        float dot = (pd.x + pd.y) + (pd.z + pd.w);

        // Up-rescale if ring content decayed far below ref.
        if (dot < 1e-30f && dot > 0.0f) {
            #pragma unroll 1
            for (int s = 64 * h; s < 64 * h + 64; ++s) ring[s * NS + j] *= 1e30f;
            ref -= 69.07755279f;   // ln(1e30)
            dot *= 1e30f;
        }

        // cum[t+1] = cum[t] + lb[t]  (Kahan, identical across replicas)
        float y  = lb_cur - cumc;
        float tt = cum + y;
        cumc = (tt - cum) - y;
        cum  = tt;

        alpha = cum + ref + __logf(dot);
        lb_cur = lb_next;
    }

    // loglik[b] = LSE_j alpha[T-1, j]  (h==0 warps hold all 128 states)
    __syncthreads();
    if (h == 0) {
        float v = alpha;
        #pragma unroll
        for (int o = 16; o > 0; o >>= 1)
            v = fmaxf(v, __shfl_xor_sync(0xffffffffu, v, o));
        if (lane == 0) pdur[w] = v;
    }
    __syncthreads();
    float m = fmaxf(fmaxf(pdur[0], pdur[1]), fmaxf(pdur[2], pdur[3]));
    if (h == 0) {
        float e = __expf(alpha - m);
        #pragma unroll
        for (int o = 16; o > 0; o >>= 1)
            e += __shfl_xor_sync(0xffffffffu, e, o);
        if (lane == 0) pdur[8 + w] = e;
    }
    __syncthreads();
    if (tid == 0) {
        float ssum = (pdur[8] + pdur[9]) + (pdur[10] + pdur[11]);
        out[b] = m + __logf(ssum);
    }
}

extern "C" void kernel_launch(void* const* d_in, const int* in_sizes, int n_in,
                              void* d_out, int out_size)
{
    const float* logB = (const float*)d_in[0];
    const float* pi   = (const float*)d_in[1];
    const float* A    = (const float*)d_in[2];
    const float* D    = (const float*)d_in[3];
    float* out = (float*)d_out;

    const size_t smem_bytes = (size_t)SMEM_FLOATS * sizeof(float);  // ~133 KB
    cudaFuncSetAttribute(hsmm_fwd_kernel,
                         cudaFuncAttributeMaxDynamicSharedMemorySize,
                         (int)smem_bytes);
    hsmm_fwd_kernel<<<NB, 512, smem_bytes>>>(logB, pi, A, D, out);
}